// round 16
// baseline (speedup 1.0000x reference)
#include <cuda_runtime.h>
#include <cuda_fp16.h>
#include <mma.h>
#include <cstdint>
using namespace nvcuda;

#define D 128
#define NSRC0 100000
#define NDST0 25000
#define NDST1 5000
#define OUTD 64

__device__ float4  g_z0[2 * NSRC0 * 32];
__device__ float4  g_z1[2 * NDST0 * 32];
__device__ float4  g_z2[2 * NDST1 * 32];
__device__ __half2 g_z0h[2 * NSRC0 * 64];   // fp16 shadow of z0 (agg gather source)
__device__ __half2 g_z1h[2 * NDST0 * 64];   // fp16 shadow of z1
__device__ float4  g_sone[2 * NDST0 * 32];
__device__ float4  g_p[2 * NDST0 * 32];
__device__ float   g_sw[2 * NDST0];
__device__ float   g_deg[2 * NDST0];
__device__ float2  g_pe_src[2 * NSRC0];
__device__ float2  g_pe_dst[2 * NDST0];
__device__ float   g_pi_src[2 * NSRC0];
__device__ float   g_pi_dst[2 * NDST0];
__device__ float2  g_nalpha[2 * NDST0];
__device__ float   g_wr[147456];
__device__ int g_cnt[2 * NDST0 + 2 * NDST1];
__device__ int g_rank[1200000];
__device__ int g_row0[NDST0 + 1];
__device__ int g_row1[NDST0 + 1];
__device__ int g_row2[NDST1 + 1];
__device__ int g_row3[NDST1 + 1];
__device__ int g_col0[500000];
__device__ int g_col1[500000];
__device__ int g_col2[100000];
__device__ int g_col3[100000];

__device__ __forceinline__ float to_tf32(float x)
{ asm("cvt.rna.tf32.f32 %0, %1;" : "=f"(x) : "f"(x)); return x; }
__device__ __forceinline__ void cp_async16(float* smem, const float* gmem)
{
    uint32_t s = (uint32_t)__cvta_generic_to_shared(smem);
    asm volatile("cp.async.cg.shared.global [%0], [%1], 16;" :: "r"(s), "l"(gmem));
}
__device__ __forceinline__ void cp_commit() { asm volatile("cp.async.commit_group;"); }
__device__ __forceinline__ void cp_wait0()  { asm volatile("cp.async.wait_group 0;"); }
__device__ __forceinline__ void cp_wait1()  { asm volatile("cp.async.wait_group 1;"); }

// ---------------------------------------------------------------------------
__global__ void round_weights_kernel(const float* __restrict__ Win,
                                     const float* __restrict__ W1,
                                     const float* __restrict__ W2,
                                     const float* __restrict__ Wout,
                                     float* __restrict__ wr)
{
    const int i = blockIdx.x * blockDim.x + threadIdx.x;
    if (i < 65536)        wr[i] = to_tf32(Win[i]);
    else if (i < 98304)   wr[i] = to_tf32(W1[i - 65536]);
    else if (i < 131072)  wr[i] = to_tf32(W2[i - 98304]);
    else if (i < 147456)  wr[i] = to_tf32(Wout[i - 131072]);
}

__global__ void hist4_kernel(const int* __restrict__ d0, const int* __restrict__ d1,
                             const int* __restrict__ d2, const int* __restrict__ d3,
                             int E0, int E1, int* __restrict__ cnt, int* __restrict__ rank)
{
    const int i = blockIdx.x * blockDim.x + threadIdx.x;
    const int t0 = E0, t1 = 2 * E0, t2 = 2 * E0 + E1, t3 = 2 * E0 + 2 * E1;
    if (i < t0)      rank[i] = atomicAdd(cnt + d0[i], 1);
    else if (i < t1) rank[i] = atomicAdd(cnt + NDST0 + d1[i - t0], 1);
    else if (i < t2) rank[i] = atomicAdd(cnt + 2 * NDST0 + d2[i - t1], 1);
    else if (i < t3) rank[i] = atomicAdd(cnt + 2 * NDST0 + NDST1 + d3[i - t2], 1);
}

__global__ void scan4_kernel(const int* __restrict__ cnt,
                             int* __restrict__ row0, int* __restrict__ row1,
                             int* __restrict__ row2, int* __restrict__ row3)
{
    __shared__ int part[1024];
    const int b = blockIdx.x;
    const int n = (b < 2) ? NDST0 : NDST1;
    const int off = (b == 0) ? 0 : (b == 1) ? NDST0 : (b == 2) ? 2 * NDST0 : 2 * NDST0 + NDST1;
    int* row = (b == 0) ? row0 : (b == 1) ? row1 : (b == 2) ? row2 : row3;
    const int t = threadIdx.x;
    const int CH = (n + 1023) / 1024;
    const int base = t * CH;
    int sum = 0;
    for (int i = 0; i < CH; ++i) { const int idx = base + i; if (idx < n) sum += cnt[off + idx]; }
    part[t] = sum;
    __syncthreads();
    for (int o = 1; o < 1024; o <<= 1) {
        int v = 0;
        if (t >= o) v = part[t - o];
        __syncthreads();
        part[t] += v;
        __syncthreads();
    }
    int run = (t == 0) ? 0 : part[t - 1];
    for (int i = 0; i < CH; ++i) {
        const int idx = base + i;
        if (idx < n) { row[idx] = run; run += cnt[off + idx]; }
    }
    if (t == 1023) row[n] = part[1023];
}

__global__ void fill4_kernel(const int* __restrict__ s0, const int* __restrict__ d0,
                             const int* __restrict__ s1, const int* __restrict__ d1,
                             const int* __restrict__ s2, const int* __restrict__ d2,
                             const int* __restrict__ s3, const int* __restrict__ d3,
                             int E0, int E1, const int* __restrict__ rank,
                             const int* __restrict__ row0, const int* __restrict__ row1,
                             const int* __restrict__ row2, const int* __restrict__ row3,
                             int* __restrict__ c0, int* __restrict__ c1,
                             int* __restrict__ c2, int* __restrict__ c3)
{
    const int i = blockIdx.x * blockDim.x + threadIdx.x;
    const int t0 = E0, t1 = 2 * E0, t2 = 2 * E0 + E1, t3 = 2 * E0 + 2 * E1;
    if (i < t0)      { c0[row0[d0[i]] + rank[i]] = s0[i]; }
    else if (i < t1) { const int j = i - t0; c1[row1[d1[j]] + rank[i]] = s1[j]; }
    else if (i < t2) { const int j = i - t1; c2[row2[d2[j]] + rank[i]] = s2[j]; }
    else if (i < t3) { const int j = i - t2; c3[row3[d3[j]] + rank[i]] = s3[j]; }
}

// ---------------------------------------------------------------------------
// Projections (fp32 z); mode = blockIdx.y + mbase
// ---------------------------------------------------------------------------
__global__ void proj2_kernel(const float4* __restrict__ zb, size_t zstride,
                             int n_src, int n_dst, int mbase,
                             const float* __restrict__ nab, const float* __restrict__ eab,
                             const float* __restrict__ iab,
                             float2* __restrict__ pe_srcb, float2* __restrict__ pe_dstb,
                             float* __restrict__ pi_srcb, float* __restrict__ pi_dstb,
                             float2* __restrict__ nalphab)
{
    const int m = blockIdx.y + mbase;
    const float4* z = zb + (size_t)m * zstride;
    const float* na = nab + (size_t)m * D * 2;
    const float* ea = eab + (size_t)m * 2 * D * 2;
    const float* ia = iab + (size_t)m * 2 * D;
    float2* pe_src = pe_srcb + (size_t)m * NSRC0;
    float*  pi_src = pi_srcb + (size_t)m * NSRC0;
    float2* pe_dst = pe_dstb + (size_t)m * NDST0;
    float*  pi_dst = pi_dstb + (size_t)m * NDST0;
    float2* nalpha = nalphab + (size_t)m * NDST0;

    const int warp = (blockIdx.x * blockDim.x + threadIdx.x) >> 5;
    const int lane = threadIdx.x & 31;
    if (warp >= n_src) return;

    const float4 z4 = z[(size_t)warp * 32 + lane];
    const float4* ea4 = reinterpret_cast<const float4*>(ea);
    const float4 e0 = ea4[lane * 2 + 0];
    const float4 e1 = ea4[lane * 2 + 1];
    float pes0 = z4.x * e0.x + z4.y * e0.z + z4.z * e1.x + z4.w * e1.z;
    float pes1 = z4.x * e0.y + z4.y * e0.w + z4.z * e1.y + z4.w * e1.w;
    const float4 d0 = ea4[64 + lane * 2 + 0];
    const float4 d1 = ea4[64 + lane * 2 + 1];
    float ped0 = z4.x * d0.x + z4.y * d0.z + z4.z * d1.x + z4.w * d1.z;
    float ped1 = z4.x * d0.y + z4.y * d0.w + z4.z * d1.y + z4.w * d1.w;
    const float4 i0 = *reinterpret_cast<const float4*>(ia + lane * 4);
    float pis = z4.x * i0.x + z4.y * i0.y + z4.z * i0.z + z4.w * i0.w;
    const float4 i1 = *reinterpret_cast<const float4*>(ia + 128 + lane * 4);
    float pid = z4.x * i1.x + z4.y * i1.y + z4.z * i1.z + z4.w * i1.w;
    const float4* na4 = reinterpret_cast<const float4*>(na);
    const float4 n0 = na4[lane * 2 + 0];
    const float4 n1 = na4[lane * 2 + 1];
    float nl0 = z4.x * n0.x + z4.y * n0.z + z4.z * n1.x + z4.w * n1.z;
    float nl1 = z4.x * n0.y + z4.y * n0.w + z4.z * n1.y + z4.w * n1.w;

#pragma unroll
    for (int off = 16; off; off >>= 1) {
        pes0 += __shfl_xor_sync(0xffffffffu, pes0, off);
        pes1 += __shfl_xor_sync(0xffffffffu, pes1, off);
        ped0 += __shfl_xor_sync(0xffffffffu, ped0, off);
        ped1 += __shfl_xor_sync(0xffffffffu, ped1, off);
        pis  += __shfl_xor_sync(0xffffffffu, pis, off);
        pid  += __shfl_xor_sync(0xffffffffu, pid, off);
        nl0  += __shfl_xor_sync(0xffffffffu, nl0, off);
        nl1  += __shfl_xor_sync(0xffffffffu, nl1, off);
    }
    if (lane == 0) {
        pe_src[warp] = make_float2(pes0, pes1);
        pi_src[warp] = pis;
        if (warp < n_dst) {
            pe_dst[warp] = make_float2(ped0, ped1);
            pi_dst[warp] = pid;
            const float mx = fmaxf(nl0, nl1);
            const float a = __expf(nl0 - mx), b = __expf(nl1 - mx);
            const float inv = 1.f / (a + b);
            nalpha[warp] = make_float2(a * inv, b * inv);
        }
    }
}

// ---------------------------------------------------------------------------
// Aggregation: gathers neighbor rows from fp16 shadow (half traffic);
// dst row (for P) stays fp32. mode = blockIdx.y + mbase.
// ---------------------------------------------------------------------------
__global__ void agg2_kernel(int n_dst, int mbase,
                            const int* __restrict__ rowA, const int* __restrict__ colA,
                            const int* __restrict__ rowB, const int* __restrict__ colB,
                            const float4* __restrict__ zb, size_t zstride,
                            const __half2* __restrict__ zhb, size_t zhstride,
                            const float2* __restrict__ pe_srcb, const float2* __restrict__ pe_dstb,
                            const float* __restrict__ pi_srcb, const float* __restrict__ pi_dstb,
                            const float2* __restrict__ nalphab,
                            float4* __restrict__ S_oneb, float4* __restrict__ Pb,
                            float* __restrict__ sw_outb, float* __restrict__ deg_outb)
{
    const int m = blockIdx.y + mbase;
    const int* rowe = m ? rowB : rowA;
    const int* cole = m ? colB : colA;
    const int* rowi = m ? rowA : rowB;
    const int* coli = m ? colA : colB;
    const float4*  z  = zb  + (size_t)m * zstride;
    const __half2* zh = zhb + (size_t)m * zhstride;
    const float2* pe_src = pe_srcb + (size_t)m * NSRC0;
    const float*  pi_src = pi_srcb + (size_t)m * NSRC0;
    const float2* pe_dst = pe_dstb + (size_t)m * NDST0;
    const float*  pi_dst = pi_dstb + (size_t)m * NDST0;
    const float2* nalpha = nalphab + (size_t)m * NDST0;
    float4* S_one = S_oneb + (size_t)m * NDST0 * 32;
    float4* P     = Pb     + (size_t)m * NDST0 * 32;
    float* sw_out  = sw_outb  + (size_t)m * NDST0;
    float* deg_out = deg_outb + (size_t)m * NDST0;

    const int d    = (blockIdx.x * blockDim.x + threadIdx.x) >> 5;
    const int lane = threadIdx.x & 31;
    if (d >= n_dst) return;

    float4 acc1 = make_float4(0.f, 0.f, 0.f, 0.f);
    float4 acce = make_float4(0.f, 0.f, 0.f, 0.f);
    float4 acci = make_float4(0.f, 0.f, 0.f, 0.f);
    float  sw   = 0.f;

    const float2 pd = pe_dst[d];
    const int re0 = rowe[d], re1 = rowe[d + 1];
    for (int c = re0; c < re1; c += 32) {
        const int nvalid = min(32, re1 - c);
        int s = 0; float a0 = 0.f, a1 = 0.f;
        if (lane < nvalid) {
            s = __ldg(cole + c + lane);
            const float2 ps = pe_src[s];
            const float l0 = ps.x + pd.x, l1 = ps.y + pd.y;
            const float mx = fmaxf(l0, l1);
            const float x0 = __expf(l0 - mx), x1 = __expf(l1 - mx);
            const float inv = 1.f / (x0 + x1);
            a0 = x0 * inv; a1 = x1 * inv; sw += a0;
        }
#pragma unroll 4
        for (int j = 0; j < nvalid; ++j) {
            const int   sj = __shfl_sync(0xffffffffu, s,  j);
            const float w0 = __shfl_sync(0xffffffffu, a0, j);
            const float w1 = __shfl_sync(0xffffffffu, a1, j);
            const uint2 raw = *reinterpret_cast<const uint2*>(zh + (size_t)sj * 64 + lane * 2);
            const float2 f0 = __half22float2(*reinterpret_cast<const __half2*>(&raw.x));
            const float2 f1 = __half22float2(*reinterpret_cast<const __half2*>(&raw.y));
            acc1.x += w0 * f0.x; acc1.y += w0 * f0.y; acc1.z += w0 * f1.x; acc1.w += w0 * f1.y;
            acce.x += w1 * f0.x; acce.y += w1 * f0.y; acce.z += w1 * f1.x; acce.w += w1 * f1.y;
        }
    }
    const float pid = pi_dst[d];
    const int ri0 = rowi[d], ri1 = rowi[d + 1];
    for (int c = ri0; c < ri1; c += 32) {
        const int nvalid = min(32, ri1 - c);
        int s = 0; float g = 0.f;
        if (lane < nvalid) {
            s = __ldg(coli + c + lane);
            const float x = pi_src[s] + pid;
            g = 1.f / (1.f + __expf(-x));
        }
#pragma unroll 4
        for (int j = 0; j < nvalid; ++j) {
            const int   sj = __shfl_sync(0xffffffffu, s, j);
            const float w  = __shfl_sync(0xffffffffu, g, j);
            const uint2 raw = *reinterpret_cast<const uint2*>(zh + (size_t)sj * 64 + lane * 2);
            const float2 f0 = __half22float2(*reinterpret_cast<const __half2*>(&raw.x));
            const float2 f1 = __half22float2(*reinterpret_cast<const __half2*>(&raw.y));
            acci.x += w * f0.x; acci.y += w * f0.y; acci.z += w * f1.x; acci.w += w * f1.y;
        }
    }
#pragma unroll
    for (int off = 16; off; off >>= 1)
        sw += __shfl_xor_sync(0xffffffffu, sw, off);

    const float2 na = nalpha[d];
    const float  nz = na.x + na.y;
    const float4 zd = z[(size_t)d * 32 + lane];
    float4 p;
    p.x = fmaxf(acce.x * acci.x, 0.f) + nz * zd.x;
    p.y = fmaxf(acce.y * acci.y, 0.f) + nz * zd.y;
    p.z = fmaxf(acce.z * acci.z, 0.f) + nz * zd.z;
    p.w = fmaxf(acce.w * acci.w, 0.f) + nz * zd.w;
    acc1.x = to_tf32(acc1.x); acc1.y = to_tf32(acc1.y);
    acc1.z = to_tf32(acc1.z); acc1.w = to_tf32(acc1.w);
    S_one[(size_t)d * 32 + lane] = acc1;
    P[(size_t)d * 32 + lane]     = p;
    if (lane == 0) { sw_out[d] = sw; deg_out[d] = (float)(re1 - re0); }
}

// ---------------------------------------------------------------------------
// wmma tf32 GEMM: BM=64, 256 threads (2M x 4N warps, tile 32x32), BK=32,
// 2-stage cp.async, up to 4 CTAs/SM. WH: also write fp16 shadow of C.
// ---------------------------------------------------------------------------
struct ModeArgs {
    const float* A0;  const float* A1;
    const float* B0;  const float* B1;
    const float* b0;  const float* b1;
    float* C0;        float* C1;
    const float* P0;  const float* P1;
    const float* sw0; const float* sw1;
    const float* dg0; const float* dg1;
    __half2* h0;      __half2* h1;
};

template <int BN, bool FUSED, bool CONV_A, bool ROUND_OUT, bool WH>
__global__ void __launch_bounds__(256, 4)
gemm64_kernel(ModeArgs ma, int M, int K)
{
    constexpr int BM  = 64, BK = 32;
    constexpr int ASP = BK + 4;
    constexpr int BNP = BN + 8;
    constexpr int ASZ = BM * ASP;
    constexpr int BSZ = BK * BNP;
    constexpr int STG = ASZ + BSZ;
    constexpr int WN  = BN / 4;
    constexpr int FN  = WN / 16;
    constexpr int FM  = 2;
    constexpr int BLD = BN / 32;

    extern __shared__ float sbuf[];
    const int mode = blockIdx.y;
    const float* A    = mode ? ma.A1 : ma.A0;
    const float* B    = mode ? ma.B1 : ma.B0;
    const float* bias = mode ? ma.b1 : ma.b0;
    float*       C    = mode ? ma.C1 : ma.C0;
    const float* P    = mode ? ma.P1 : ma.P0;
    const float* sw   = mode ? ma.sw1 : ma.sw0;
    const float* deg  = mode ? ma.dg1 : ma.dg0;
    __half2*     H    = mode ? ma.h1 : ma.h0;

    const int tid    = threadIdx.x;
    const int warp   = tid >> 5;
    const int warp_m = warp & 1;
    const int warp_n = warp >> 1;
    const int m0     = blockIdx.x * BM;

    wmma::fragment<wmma::accumulator, 16, 16, 8, float> acc[FM][FN];
#pragma unroll
    for (int i = 0; i < FM; ++i)
#pragma unroll
        for (int j = 0; j < FN; ++j) wmma::fill_fragment(acc[i][j], 0.f);

    auto load_tiles = [&](int stage, int k0) {
        float* As = sbuf + stage * STG;
        float* Bs = As + ASZ;
#pragma unroll
        for (int i = 0; i < 2; ++i) {
            const int c = tid + i * 256;
            const int row = c >> 3, cc = (c & 7) * 4;
            int gr = m0 + row;
            gr = gr < M ? gr : M - 1;
            cp_async16(As + row * ASP + cc, A + (size_t)gr * K + k0 + cc);
        }
#pragma unroll
        for (int i = 0; i < BLD; ++i) {
            const int c = tid + i * 256;
            const int row = c / (BN / 4), cc = (c % (BN / 4)) * 4;
            cp_async16(Bs + row * BNP + cc, B + (size_t)(k0 + row) * BN + cc);
        }
        cp_commit();
    };

    const int NT = K / BK;
    load_tiles(0, 0);
    for (int t = 0; t < NT; ++t) {
        const int st = t & 1;
        if (t + 1 < NT) { load_tiles(st ^ 1, (t + 1) * BK); cp_wait1(); }
        else cp_wait0();
        __syncthreads();

        float* As = sbuf + st * STG;
        const float* Bs = As + ASZ;
        if (CONV_A) {
#pragma unroll
            for (int i = 0; i < 2; ++i) {
                const int c = tid + i * 256;
                const int row = c >> 3, cc = (c & 7) * 4;
                float4 v = *reinterpret_cast<const float4*>(As + row * ASP + cc);
                v.x = to_tf32(v.x); v.y = to_tf32(v.y);
                v.z = to_tf32(v.z); v.w = to_tf32(v.w);
                *reinterpret_cast<float4*>(As + row * ASP + cc) = v;
            }
            __syncthreads();
        }

#pragma unroll
        for (int ks = 0; ks < 4; ++ks) {
            wmma::fragment<wmma::matrix_a, 16, 16, 8, wmma::precision::tf32, wmma::row_major> af[FM];
            wmma::fragment<wmma::matrix_b, 16, 16, 8, wmma::precision::tf32, wmma::row_major> bf[FN];
#pragma unroll
            for (int i = 0; i < FM; ++i)
                wmma::load_matrix_sync(af[i], As + (warp_m * 32 + i * 16) * ASP + ks * 8, ASP);
#pragma unroll
            for (int j = 0; j < FN; ++j)
                wmma::load_matrix_sync(bf[j], Bs + (ks * 8) * BNP + warp_n * WN + j * 16, BNP);
#pragma unroll
            for (int i = 0; i < FM; ++i)
#pragma unroll
                for (int j = 0; j < FN; ++j)
                    wmma::mma_sync(acc[i][j], af[i], bf[j], acc[i][j]);
        }
        __syncthreads();
    }

    float* Cs = sbuf;
#pragma unroll
    for (int i = 0; i < FM; ++i)
#pragma unroll
        for (int j = 0; j < FN; ++j)
            wmma::store_matrix_sync(Cs + (warp_m * 32 + i * 16) * BNP + warp_n * WN + j * 16,
                                    acc[i][j], BNP, wmma::mem_row_major);
    __syncthreads();

#pragma unroll
    for (int i = tid; i < BM * BN / 4; i += 256) {
        const int row = i / (BN / 4), cc = (i % (BN / 4)) * 4;
        const int grow = m0 + row;
        if (grow < M) {
            float4 v = *reinterpret_cast<const float4*>(Cs + row * BNP + cc);
            const float4 bb = *reinterpret_cast<const float4*>(bias + cc);
            if (FUSED) {
                const float swv  = sw[grow];
                const float invd = 1.f / fmaxf(deg[grow], 1.f);
                const float4 pp  = *reinterpret_cast<const float4*>(P + (size_t)grow * BN + cc);
                v.x = 0.5f * (fmaxf((v.x + swv * bb.x) * invd, 0.f) + pp.x);
                v.y = 0.5f * (fmaxf((v.y + swv * bb.y) * invd, 0.f) + pp.y);
                v.z = 0.5f * (fmaxf((v.z + swv * bb.z) * invd, 0.f) + pp.z);
                v.w = 0.5f * (fmaxf((v.w + swv * bb.w) * invd, 0.f) + pp.w);
            } else { v.x += bb.x; v.y += bb.y; v.z += bb.z; v.w += bb.w; }
            if (ROUND_OUT) {
                v.x = to_tf32(v.x); v.y = to_tf32(v.y);
                v.z = to_tf32(v.z); v.w = to_tf32(v.w);
            }
            *reinterpret_cast<float4*>(C + (size_t)grow * BN + cc) = v;
            if (WH) {
                union { __half2 h[2]; uint2 u; } pk;
                pk.h[0] = __floats2half2_rn(v.x, v.y);
                pk.h[1] = __floats2half2_rn(v.z, v.w);
                *reinterpret_cast<uint2*>(H + (size_t)grow * (BN / 2) + (cc >> 1)) = pk.u;
            }
        }
    }
}

// ---------------------------------------------------------------------------
extern "C" void kernel_launch(void* const* d_in, const int* in_sizes, int n_in,
                              void* d_out, int out_size)
{
    const float* feat = (const float*)d_in[0];
    const int* src0[2] = {(const int*)d_in[1], (const int*)d_in[3]};
    const int* dst0[2] = {(const int*)d_in[2], (const int*)d_in[4]};
    const int* src1[2] = {(const int*)d_in[5], (const int*)d_in[7]};
    const int* dst1[2] = {(const int*)d_in[6], (const int*)d_in[8]};
    const int E0 = in_sizes[1];
    const int E1 = in_sizes[5];

    const int b = n_in - 14;
    const float* Win  = (const float*)d_in[b + 0];
    const float* b_in = (const float*)d_in[b + 1];
    const float* na1  = (const float*)d_in[b + 2];
    const float* ea1  = (const float*)d_in[b + 3];
    const float* ia1  = (const float*)d_in[b + 4];
    const float* W1   = (const float*)d_in[b + 5];
    const float* b1   = (const float*)d_in[b + 6];
    const float* na2  = (const float*)d_in[b + 7];
    const float* ea2  = (const float*)d_in[b + 8];
    const float* ia2  = (const float*)d_in[b + 9];
    const float* W2   = (const float*)d_in[b + 10];
    const float* b2   = (const float*)d_in[b + 11];
    const float* Wout = (const float*)d_in[b + 12];
    const float* bout = (const float*)d_in[b + 13];

    const int F = in_sizes[b + 0] / (2 * D);
    const int n_src0 = in_sizes[0] / F;

    float4 *z0, *z1, *z2, *sone, *P4;
    __half2 *z0h, *z1h;
    float *sw, *deg, *pi_src, *pi_dst, *wr;
    float2 *pe_src, *pe_dst, *nalpha;
    int *cnt, *rank, *row[4], *col[4];
    cudaGetSymbolAddress((void**)&z0, g_z0);
    cudaGetSymbolAddress((void**)&z1, g_z1);
    cudaGetSymbolAddress((void**)&z2, g_z2);
    cudaGetSymbolAddress((void**)&z0h, g_z0h);
    cudaGetSymbolAddress((void**)&z1h, g_z1h);
    cudaGetSymbolAddress((void**)&sone, g_sone);
    cudaGetSymbolAddress((void**)&P4, g_p);
    cudaGetSymbolAddress((void**)&sw, g_sw);
    cudaGetSymbolAddress((void**)&deg, g_deg);
    cudaGetSymbolAddress((void**)&pe_src, g_pe_src);
    cudaGetSymbolAddress((void**)&pe_dst, g_pe_dst);
    cudaGetSymbolAddress((void**)&pi_src, g_pi_src);
    cudaGetSymbolAddress((void**)&pi_dst, g_pi_dst);
    cudaGetSymbolAddress((void**)&nalpha, g_nalpha);
    cudaGetSymbolAddress((void**)&wr, g_wr);
    cudaGetSymbolAddress((void**)&cnt, g_cnt);
    cudaGetSymbolAddress((void**)&rank, g_rank);
    cudaGetSymbolAddress((void**)&row[0], g_row0);
    cudaGetSymbolAddress((void**)&row[1], g_row1);
    cudaGetSymbolAddress((void**)&row[2], g_row2);
    cudaGetSymbolAddress((void**)&row[3], g_row3);
    cudaGetSymbolAddress((void**)&col[0], g_col0);
    cudaGetSymbolAddress((void**)&col[1], g_col1);
    cudaGetSymbolAddress((void**)&col[2], g_col2);
    cudaGetSymbolAddress((void**)&col[3], g_col3);

    const float* Win_r  = wr;
    const float* W1_r   = wr + 65536;
    const float* W2_r   = wr + 98304;
    const float* Wout_r = wr + 131072;

    float4*  z0m[2]  = {z0,   z0   + (size_t)NSRC0 * 32};
    float4*  z1m[2]  = {z1,   z1   + (size_t)NDST0 * 32};
    float4*  z2m[2]  = {z2,   z2   + (size_t)NDST1 * 32};
    __half2* z0hm[2] = {z0h,  z0h  + (size_t)NSRC0 * 64};
    __half2* z1hm[2] = {z1h,  z1h  + (size_t)NDST0 * 64};
    float4*  sonem[2] = {sone, sone + (size_t)NDST0 * 32};
    float4*  Pm[2]    = {P4,   P4   + (size_t)NDST0 * 32};
    float*   swm[2]   = {sw,   sw   + NDST0};
    float*   degm[2]  = {deg,  deg  + NDST0};

    constexpr int SM128 = 2 * (64 * 36 + 32 * 136) * 4;
    constexpr int SM64  = 2 * (64 * 36 + 32 * 72) * 4;
    cudaFuncSetAttribute(gemm64_kernel<128, false, true, false, true>,
                         cudaFuncAttributeMaxDynamicSharedMemorySize, SM128);
    cudaFuncSetAttribute(gemm64_kernel<128, true, false, false, true>,
                         cudaFuncAttributeMaxDynamicSharedMemorySize, SM128);
    cudaFuncSetAttribute(gemm64_kernel<128, true, false, true, false>,
                         cudaFuncAttributeMaxDynamicSharedMemorySize, SM128);
    cudaFuncSetAttribute(gemm64_kernel<64, false, false, false, false>,
                         cudaFuncAttributeMaxDynamicSharedMemorySize, SM64);

    float* out = (float*)d_out;
    const int Etot = 2 * E0 + 2 * E1;

    round_weights_kernel<<<576, 256>>>(Win, W1, W2, Wout, wr);
    cudaMemsetAsync(cnt, 0, sizeof(int) * (2 * NDST0 + 2 * NDST1));
    hist4_kernel<<<(Etot + 255) / 256, 256>>>(dst0[0], dst0[1], dst1[0], dst1[1],
                                              E0, E1, cnt, rank);
    scan4_kernel<<<4, 1024>>>(cnt, row[0], row[1], row[2], row[3]);

    // ---- Input GEMM (writes z0 + fp16 shadow z0h) ----
    {
        ModeArgs ma = {feat, feat,
                       Win_r, Win_r + (size_t)F * D, b_in, b_in + D,
                       (float*)z0m[0], (float*)z0m[1],
                       nullptr, nullptr, nullptr, nullptr, nullptr, nullptr,
                       z0hm[0], z0hm[1]};
        gemm64_kernel<128, false, true, false, true>
            <<<dim3((n_src0 + 63) / 64, 2), 256, SM128>>>(ma, n_src0, F);
    }

    fill4_kernel<<<(Etot + 255) / 256, 256>>>(src0[0], dst0[0], src0[1], dst0[1],
                                              src1[0], dst1[0], src1[1], dst1[1],
                                              E0, E1, rank,
                                              row[0], row[1], row[2], row[3],
                                              col[0], col[1], col[2], col[3]);

    // ---- Layer 1: per-mode sequential proj -> agg (fp16 gathers) ----
    for (int m = 0; m < 2; ++m) {
        proj2_kernel<<<dim3((n_src0 * 32 + 255) / 256, 1), 256>>>(
            z0, (size_t)NSRC0 * 32, n_src0, NDST0, m,
            na1, ea1, ia1, pe_src, pe_dst, pi_src, pi_dst, nalpha);
        agg2_kernel<<<dim3((NDST0 * 32 + 255) / 256, 1), 256>>>(
            NDST0, m, row[0], col[0], row[1], col[1],
            z0, (size_t)NSRC0 * 32, z0h, (size_t)NSRC0 * 64,
            pe_src, pe_dst, pi_src, pi_dst, nalpha, sone, P4, sw, deg);
    }

    // ---- Layer 1 GEMM (writes z1 + fp16 shadow z1h) ----
    {
        ModeArgs ma = {(const float*)sonem[0], (const float*)sonem[1],
                       W1_r, W1_r + (size_t)D * D, b1, b1 + D,
                       (float*)z1m[0], (float*)z1m[1],
                       (const float*)Pm[0], (const float*)Pm[1],
                       swm[0], swm[1], degm[0], degm[1],
                       z1hm[0], z1hm[1]};
        gemm64_kernel<128, true, false, false, true>
            <<<dim3((NDST0 + 63) / 64, 2), 256, SM128>>>(ma, NDST0, D);
    }

    // ---- Layer 2: proj + agg (fp16 gathers from z1h) ----
    proj2_kernel<<<dim3((NDST0 * 32 + 255) / 256, 2), 256>>>(
        z1, (size_t)NDST0 * 32, NDST0, NDST1, 0,
        na2, ea2, ia2, pe_src, pe_dst, pi_src, pi_dst, nalpha);
    agg2_kernel<<<dim3((NDST1 * 32 + 255) / 256, 2), 256>>>(
        NDST1, 0, row[2], col[2], row[3], col[3],
        z1, (size_t)NDST0 * 32, z1h, (size_t)NDST0 * 64,
        pe_src, pe_dst, pi_src, pi_dst, nalpha, sone, P4, sw, deg);

    // ---- Layer 2 GEMM (z2 rounded at write; no half needed) ----
    {
        ModeArgs ma = {(const float*)sonem[0], (const float*)sonem[1],
                       W2_r, W2_r + (size_t)D * D, b2, b2 + D,
                       (float*)z2m[0], (float*)z2m[1],
                       (const float*)Pm[0], (const float*)Pm[1],
                       swm[0], swm[1], degm[0], degm[1],
                       nullptr, nullptr};
        gemm64_kernel<128, true, false, true, false>
            <<<dim3((NDST1 + 63) / 64, 2), 256, SM128>>>(ma, NDST1, D);
    }

    // ---- Output GEMM ----
    {
        ModeArgs ma = {(const float*)z2m[0], (const float*)z2m[1],
                       Wout_r, Wout_r + (size_t)D * OUTD, bout, bout + OUTD,
                       out, out + (size_t)NDST1 * OUTD,
                       nullptr, nullptr, nullptr, nullptr, nullptr, nullptr,
                       nullptr, nullptr};
        gemm64_kernel<64, false, false, false, false>
            <<<dim3((NDST1 + 63) / 64, 2), 256, SM64>>>(ma, NDST1, D);
    }
    (void)out_size;
}

// round 17
// speedup vs baseline: 1.4513x; 1.4513x over previous
#include <cuda_runtime.h>
#include <cuda_fp16.h>
#include <mma.h>
#include <cstdint>
using namespace nvcuda;

#define D 128
#define NSRC0 100000
#define NDST0 25000
#define NDST1 5000
#define OUTD 64

__device__ float4  g_z0[2 * NSRC0 * 32];
__device__ float4  g_z1[2 * NDST0 * 32];
__device__ float4  g_z2[2 * NDST1 * 32];
__device__ __half  g_feath[(size_t)NSRC0 * 256];     // fp16 copy of feat (GEMM A)
__device__ __half2 g_soneh[2 * NDST0 * 64];          // fp16 S_one (GEMM A)
__device__ __half2 g_z2h[2 * NDST1 * 64];            // fp16 z2 (GEMM A)
__device__ float4  g_p[2 * NDST0 * 32];
__device__ float   g_sw[2 * NDST0];
__device__ float   g_deg[2 * NDST0];
__device__ float2  g_pe_src[2 * NSRC0];
__device__ float2  g_pe_dst[2 * NDST0];
__device__ float   g_pi_src[2 * NSRC0];
__device__ float   g_pi_dst[2 * NDST0];
__device__ float2  g_nalpha[2 * NDST0];
__device__ __half  g_wrh[147456];                    // fp16 weights
__device__ int g_cnt[2 * NDST0 + 2 * NDST1];
__device__ int g_rank[1200000];
__device__ int g_row0[NDST0 + 1];
__device__ int g_row1[NDST0 + 1];
__device__ int g_row2[NDST1 + 1];
__device__ int g_row3[NDST1 + 1];
__device__ int g_col0[500000];
__device__ int g_col1[500000];
__device__ int g_col2[100000];
__device__ int g_col3[100000];

__device__ __forceinline__ void cp_async16h(__half* smem, const __half* gmem)
{
    uint32_t s = (uint32_t)__cvta_generic_to_shared(smem);
    asm volatile("cp.async.cg.shared.global [%0], [%1], 16;" :: "r"(s), "l"(gmem));
}
__device__ __forceinline__ void cp_commit() { asm volatile("cp.async.commit_group;"); }
__device__ __forceinline__ void cp_wait0()  { asm volatile("cp.async.wait_group 0;"); }
__device__ __forceinline__ void cp_wait1()  { asm volatile("cp.async.wait_group 1;"); }

// ---------------------------------------------------------------------------
// Prepass: fp16 weights + fp16 feat copy
// ---------------------------------------------------------------------------
__global__ void round_weights_kernel(const float* __restrict__ Win,
                                     const float* __restrict__ W1,
                                     const float* __restrict__ W2,
                                     const float* __restrict__ Wout,
                                     __half* __restrict__ wh)
{
    const int i = blockIdx.x * blockDim.x + threadIdx.x;
    if (i < 65536)        wh[i] = __float2half(Win[i]);
    else if (i < 98304)   wh[i] = __float2half(W1[i - 65536]);
    else if (i < 131072)  wh[i] = __float2half(W2[i - 98304]);
    else if (i < 147456)  wh[i] = __float2half(Wout[i - 131072]);
}

__global__ void feat_half_kernel(const float4* __restrict__ feat, __half* __restrict__ fh,
                                 int n4)
{
    const int i = blockIdx.x * blockDim.x + threadIdx.x;
    if (i < n4) {
        const float4 v = feat[i];
        union { __half2 h[2]; uint2 u; } pk;
        pk.h[0] = __floats2half2_rn(v.x, v.y);
        pk.h[1] = __floats2half2_rn(v.z, v.w);
        *reinterpret_cast<uint2*>(fh + (size_t)i * 4) = pk.u;
    }
}

// ---------------------------------------------------------------------------
// Batched CSR build
// ---------------------------------------------------------------------------
__global__ void hist4_kernel(const int* __restrict__ d0, const int* __restrict__ d1,
                             const int* __restrict__ d2, const int* __restrict__ d3,
                             int E0, int E1, int* __restrict__ cnt, int* __restrict__ rank)
{
    const int i = blockIdx.x * blockDim.x + threadIdx.x;
    const int t0 = E0, t1 = 2 * E0, t2 = 2 * E0 + E1, t3 = 2 * E0 + 2 * E1;
    if (i < t0)      rank[i] = atomicAdd(cnt + d0[i], 1);
    else if (i < t1) rank[i] = atomicAdd(cnt + NDST0 + d1[i - t0], 1);
    else if (i < t2) rank[i] = atomicAdd(cnt + 2 * NDST0 + d2[i - t1], 1);
    else if (i < t3) rank[i] = atomicAdd(cnt + 2 * NDST0 + NDST1 + d3[i - t2], 1);
}

__global__ void scan4_kernel(const int* __restrict__ cnt,
                             int* __restrict__ row0, int* __restrict__ row1,
                             int* __restrict__ row2, int* __restrict__ row3)
{
    __shared__ int part[1024];
    const int b = blockIdx.x;
    const int n = (b < 2) ? NDST0 : NDST1;
    const int off = (b == 0) ? 0 : (b == 1) ? NDST0 : (b == 2) ? 2 * NDST0 : 2 * NDST0 + NDST1;
    int* row = (b == 0) ? row0 : (b == 1) ? row1 : (b == 2) ? row2 : row3;
    const int t = threadIdx.x;
    const int CH = (n + 1023) / 1024;
    const int base = t * CH;
    int sum = 0;
    for (int i = 0; i < CH; ++i) { const int idx = base + i; if (idx < n) sum += cnt[off + idx]; }
    part[t] = sum;
    __syncthreads();
    for (int o = 1; o < 1024; o <<= 1) {
        int v = 0;
        if (t >= o) v = part[t - o];
        __syncthreads();
        part[t] += v;
        __syncthreads();
    }
    int run = (t == 0) ? 0 : part[t - 1];
    for (int i = 0; i < CH; ++i) {
        const int idx = base + i;
        if (idx < n) { row[idx] = run; run += cnt[off + idx]; }
    }
    if (t == 1023) row[n] = part[1023];
}

__global__ void fill4_kernel(const int* __restrict__ s0, const int* __restrict__ d0,
                             const int* __restrict__ s1, const int* __restrict__ d1,
                             const int* __restrict__ s2, const int* __restrict__ d2,
                             const int* __restrict__ s3, const int* __restrict__ d3,
                             int E0, int E1, const int* __restrict__ rank,
                             const int* __restrict__ row0, const int* __restrict__ row1,
                             const int* __restrict__ row2, const int* __restrict__ row3,
                             int* __restrict__ c0, int* __restrict__ c1,
                             int* __restrict__ c2, int* __restrict__ c3)
{
    const int i = blockIdx.x * blockDim.x + threadIdx.x;
    const int t0 = E0, t1 = 2 * E0, t2 = 2 * E0 + E1, t3 = 2 * E0 + 2 * E1;
    if (i < t0)      { c0[row0[d0[i]] + rank[i]] = s0[i]; }
    else if (i < t1) { const int j = i - t0; c1[row1[d1[j]] + rank[i]] = s1[j]; }
    else if (i < t2) { const int j = i - t1; c2[row2[d2[j]] + rank[i]] = s2[j]; }
    else if (i < t3) { const int j = i - t2; c3[row3[d3[j]] + rank[i]] = s3[j]; }
}

// ---------------------------------------------------------------------------
// Projections (fp32 z); mode = blockIdx.y + mbase
// ---------------------------------------------------------------------------
__global__ void proj2_kernel(const float4* __restrict__ zb, size_t zstride,
                             int n_src, int n_dst, int mbase,
                             const float* __restrict__ nab, const float* __restrict__ eab,
                             const float* __restrict__ iab,
                             float2* __restrict__ pe_srcb, float2* __restrict__ pe_dstb,
                             float* __restrict__ pi_srcb, float* __restrict__ pi_dstb,
                             float2* __restrict__ nalphab)
{
    const int m = blockIdx.y + mbase;
    const float4* z = zb + (size_t)m * zstride;
    const float* na = nab + (size_t)m * D * 2;
    const float* ea = eab + (size_t)m * 2 * D * 2;
    const float* ia = iab + (size_t)m * 2 * D;
    float2* pe_src = pe_srcb + (size_t)m * NSRC0;
    float*  pi_src = pi_srcb + (size_t)m * NSRC0;
    float2* pe_dst = pe_dstb + (size_t)m * NDST0;
    float*  pi_dst = pi_dstb + (size_t)m * NDST0;
    float2* nalpha = nalphab + (size_t)m * NDST0;

    const int warp = (blockIdx.x * blockDim.x + threadIdx.x) >> 5;
    const int lane = threadIdx.x & 31;
    if (warp >= n_src) return;

    const float4 z4 = z[(size_t)warp * 32 + lane];
    const float4* ea4 = reinterpret_cast<const float4*>(ea);
    const float4 e0 = ea4[lane * 2 + 0];
    const float4 e1 = ea4[lane * 2 + 1];
    float pes0 = z4.x * e0.x + z4.y * e0.z + z4.z * e1.x + z4.w * e1.z;
    float pes1 = z4.x * e0.y + z4.y * e0.w + z4.z * e1.y + z4.w * e1.w;
    const float4 d0 = ea4[64 + lane * 2 + 0];
    const float4 d1 = ea4[64 + lane * 2 + 1];
    float ped0 = z4.x * d0.x + z4.y * d0.z + z4.z * d1.x + z4.w * d1.z;
    float ped1 = z4.x * d0.y + z4.y * d0.w + z4.z * d1.y + z4.w * d1.w;
    const float4 i0 = *reinterpret_cast<const float4*>(ia + lane * 4);
    float pis = z4.x * i0.x + z4.y * i0.y + z4.z * i0.z + z4.w * i0.w;
    const float4 i1 = *reinterpret_cast<const float4*>(ia + 128 + lane * 4);
    float pid = z4.x * i1.x + z4.y * i1.y + z4.z * i1.z + z4.w * i1.w;
    const float4* na4 = reinterpret_cast<const float4*>(na);
    const float4 n0 = na4[lane * 2 + 0];
    const float4 n1 = na4[lane * 2 + 1];
    float nl0 = z4.x * n0.x + z4.y * n0.z + z4.z * n1.x + z4.w * n1.z;
    float nl1 = z4.x * n0.y + z4.y * n0.w + z4.z * n1.y + z4.w * n1.w;

#pragma unroll
    for (int off = 16; off; off >>= 1) {
        pes0 += __shfl_xor_sync(0xffffffffu, pes0, off);
        pes1 += __shfl_xor_sync(0xffffffffu, pes1, off);
        ped0 += __shfl_xor_sync(0xffffffffu, ped0, off);
        ped1 += __shfl_xor_sync(0xffffffffu, ped1, off);
        pis  += __shfl_xor_sync(0xffffffffu, pis, off);
        pid  += __shfl_xor_sync(0xffffffffu, pid, off);
        nl0  += __shfl_xor_sync(0xffffffffu, nl0, off);
        nl1  += __shfl_xor_sync(0xffffffffu, nl1, off);
    }
    if (lane == 0) {
        pe_src[warp] = make_float2(pes0, pes1);
        pi_src[warp] = pis;
        if (warp < n_dst) {
            pe_dst[warp] = make_float2(ped0, ped1);
            pi_dst[warp] = pid;
            const float mx = fmaxf(nl0, nl1);
            const float a = __expf(nl0 - mx), b = __expf(nl1 - mx);
            const float inv = 1.f / (a + b);
            nalpha[warp] = make_float2(a * inv, b * inv);
        }
    }
}

// ---------------------------------------------------------------------------
// Aggregation (fp32 gathers); writes S_one as fp16 (GEMM A operand).
// ---------------------------------------------------------------------------
__global__ void agg2_kernel(int n_dst, int mbase,
                            const int* __restrict__ rowA, const int* __restrict__ colA,
                            const int* __restrict__ rowB, const int* __restrict__ colB,
                            const float4* __restrict__ zb, size_t zstride,
                            const float2* __restrict__ pe_srcb, const float2* __restrict__ pe_dstb,
                            const float* __restrict__ pi_srcb, const float* __restrict__ pi_dstb,
                            const float2* __restrict__ nalphab,
                            __half2* __restrict__ S_oneh, float4* __restrict__ Pb,
                            float* __restrict__ sw_outb, float* __restrict__ deg_outb)
{
    const int m = blockIdx.y + mbase;
    const int* rowe = m ? rowB : rowA;
    const int* cole = m ? colB : colA;
    const int* rowi = m ? rowA : rowB;
    const int* coli = m ? colA : colB;
    const float4* z = zb + (size_t)m * zstride;
    const float2* pe_src = pe_srcb + (size_t)m * NSRC0;
    const float*  pi_src = pi_srcb + (size_t)m * NSRC0;
    const float2* pe_dst = pe_dstb + (size_t)m * NDST0;
    const float*  pi_dst = pi_dstb + (size_t)m * NDST0;
    const float2* nalpha = nalphab + (size_t)m * NDST0;
    __half2* S1h = S_oneh + (size_t)m * NDST0 * 64;
    float4* P    = Pb     + (size_t)m * NDST0 * 32;
    float* sw_out  = sw_outb  + (size_t)m * NDST0;
    float* deg_out = deg_outb + (size_t)m * NDST0;

    const int d    = (blockIdx.x * blockDim.x + threadIdx.x) >> 5;
    const int lane = threadIdx.x & 31;
    if (d >= n_dst) return;

    float4 acc1 = make_float4(0.f, 0.f, 0.f, 0.f);
    float4 acce = make_float4(0.f, 0.f, 0.f, 0.f);
    float4 acci = make_float4(0.f, 0.f, 0.f, 0.f);
    float  sw   = 0.f;

    const float2 pd = pe_dst[d];
    const int re0 = rowe[d], re1 = rowe[d + 1];
    for (int c = re0; c < re1; c += 32) {
        const int nvalid = min(32, re1 - c);
        int s = 0; float a0 = 0.f, a1 = 0.f;
        if (lane < nvalid) {
            s = __ldg(cole + c + lane);
            const float2 ps = pe_src[s];
            const float l0 = ps.x + pd.x, l1 = ps.y + pd.y;
            const float mx = fmaxf(l0, l1);
            const float x0 = __expf(l0 - mx), x1 = __expf(l1 - mx);
            const float inv = 1.f / (x0 + x1);
            a0 = x0 * inv; a1 = x1 * inv; sw += a0;
        }
#pragma unroll 4
        for (int j = 0; j < nvalid; ++j) {
            const int   sj = __shfl_sync(0xffffffffu, s,  j);
            const float w0 = __shfl_sync(0xffffffffu, a0, j);
            const float w1 = __shfl_sync(0xffffffffu, a1, j);
            const float4 z4 = z[(size_t)sj * 32 + lane];
            acc1.x += w0 * z4.x; acc1.y += w0 * z4.y; acc1.z += w0 * z4.z; acc1.w += w0 * z4.w;
            acce.x += w1 * z4.x; acce.y += w1 * z4.y; acce.z += w1 * z4.z; acce.w += w1 * z4.w;
        }
    }
    const float pid = pi_dst[d];
    const int ri0 = rowi[d], ri1 = rowi[d + 1];
    for (int c = ri0; c < ri1; c += 32) {
        const int nvalid = min(32, ri1 - c);
        int s = 0; float g = 0.f;
        if (lane < nvalid) {
            s = __ldg(coli + c + lane);
            const float x = pi_src[s] + pid;
            g = 1.f / (1.f + __expf(-x));
        }
#pragma unroll 4
        for (int j = 0; j < nvalid; ++j) {
            const int   sj = __shfl_sync(0xffffffffu, s, j);
            const float w  = __shfl_sync(0xffffffffu, g, j);
            const float4 z4 = z[(size_t)sj * 32 + lane];
            acci.x += w * z4.x; acci.y += w * z4.y; acci.z += w * z4.z; acci.w += w * z4.w;
        }
    }
#pragma unroll
    for (int off = 16; off; off >>= 1)
        sw += __shfl_xor_sync(0xffffffffu, sw, off);

    const float2 na = nalpha[d];
    const float  nz = na.x + na.y;
    const float4 zd = z[(size_t)d * 32 + lane];
    float4 p;
    p.x = fmaxf(acce.x * acci.x, 0.f) + nz * zd.x;
    p.y = fmaxf(acce.y * acci.y, 0.f) + nz * zd.y;
    p.z = fmaxf(acce.z * acci.z, 0.f) + nz * zd.z;
    p.w = fmaxf(acce.w * acci.w, 0.f) + nz * zd.w;

    union { __half2 h[2]; uint2 u; } pk;
    pk.h[0] = __floats2half2_rn(acc1.x, acc1.y);
    pk.h[1] = __floats2half2_rn(acc1.z, acc1.w);
    *reinterpret_cast<uint2*>(S1h + (size_t)d * 64 + lane * 2) = pk.u;

    P[(size_t)d * 32 + lane] = p;
    if (lane == 0) { sw_out[d] = sw; deg_out[d] = (float)(re1 - re0); }
}

// ---------------------------------------------------------------------------
// fp16 wmma GEMM: BM=64, BK=32, 256 threads (2M x 4N warps, tile 32x32),
// m16n16k16 HMMA, fp32 accum, 2-stage cp.async. grid.y = mode.
// A and B are fp16; C fp32. WH: also emit fp16 copy of C.
// ---------------------------------------------------------------------------
struct ModeArgsH {
    const __half* A0; const __half* A1;
    const __half* B0; const __half* B1;
    const float* b0;  const float* b1;
    float* C0;        float* C1;
    const float* P0;  const float* P1;
    const float* sw0; const float* sw1;
    const float* dg0; const float* dg1;
    __half2* h0;      __half2* h1;
};

template <int BN, bool FUSED, bool WH>
__global__ void __launch_bounds__(256)
gemm64h_kernel(ModeArgsH ma, int M, int K)
{
    constexpr int BM  = 64, BK = 32;
    constexpr int ASP = BK + 8;                 // halves (40) -> 80B row stride
    constexpr int BNP = BN + 8;                 // halves
    constexpr int ASZ = BM * ASP;               // halves
    constexpr int BSZ = BK * BNP;
    constexpr int STG = ASZ + BSZ;
    constexpr int WN  = BN / 4;                 // 32 / 16
    constexpr int FN  = WN / 16;                // 2 / 1
    constexpr int FM  = 2;
    constexpr int ALD = BM * BK / 8 / 256;      // A 16B-chunks per thread (1)
    constexpr int BLD = BK * BN / 8 / 256;      // B chunks per thread (2 / 1)

    extern __shared__ float sbuf_f[];
    __half* sbuf = reinterpret_cast<__half*>(sbuf_f);

    const int mode = blockIdx.y;
    const __half* A   = mode ? ma.A1 : ma.A0;
    const __half* B   = mode ? ma.B1 : ma.B0;
    const float* bias = mode ? ma.b1 : ma.b0;
    float*       C    = mode ? ma.C1 : ma.C0;
    const float* P    = mode ? ma.P1 : ma.P0;
    const float* sw   = mode ? ma.sw1 : ma.sw0;
    const float* deg  = mode ? ma.dg1 : ma.dg0;
    __half2*     H    = mode ? ma.h1 : ma.h0;

    const int tid    = threadIdx.x;
    const int warp   = tid >> 5;
    const int warp_m = warp & 1;
    const int warp_n = warp >> 1;
    const int m0     = blockIdx.x * BM;

    wmma::fragment<wmma::accumulator, 16, 16, 16, float> acc[FM][FN];
#pragma unroll
    for (int i = 0; i < FM; ++i)
#pragma unroll
        for (int j = 0; j < FN; ++j) wmma::fill_fragment(acc[i][j], 0.f);

    auto load_tiles = [&](int stage, int k0) {
        __half* As = sbuf + stage * STG;
        __half* Bs = As + ASZ;
        // A: 64 rows x 4 chunks (8 halves each) = 256 chunks, 1/thread
#pragma unroll
        for (int i = 0; i < ALD; ++i) {
            const int c = tid + i * 256;
            const int row = c >> 2, kc = (c & 3) * 8;
            int gr = m0 + row;
            gr = gr < M ? gr : M - 1;
            cp_async16h(As + row * ASP + kc, A + (size_t)gr * K + k0 + kc);
        }
        // B: 32 rows x (BN/8) chunks
#pragma unroll
        for (int i = 0; i < BLD; ++i) {
            const int c = tid + i * 256;
            const int row = c / (BN / 8), cc = (c % (BN / 8)) * 8;
            cp_async16h(Bs + row * BNP + cc, B + (size_t)(k0 + row) * BN + cc);
        }
        cp_commit();
    };

    const int NT = K / BK;
    load_tiles(0, 0);
    for (int t = 0; t < NT; ++t) {
        const int st = t & 1;
        if (t + 1 < NT) { load_tiles(st ^ 1, (t + 1) * BK); cp_wait1(); }
        else cp_wait0();
        __syncthreads();

        const __half* As = sbuf + st * STG;
        const __half* Bs = As + ASZ;
#pragma unroll
        for (int ks = 0; ks < 2; ++ks) {
            wmma::fragment<wmma::matrix_a, 16, 16, 16, __half, wmma::row_major> af[FM];
            wmma::fragment<wmma::matrix_b, 16, 16, 16, __half, wmma::row_major> bf[FN];
#pragma unroll
            for (int i = 0; i < FM; ++i)
                wmma::load_matrix_sync(af[i], As + (warp_m * 32 + i * 16) * ASP + ks * 16, ASP);
#pragma unroll
            for (int j = 0; j < FN; ++j)
                wmma::load_matrix_sync(bf[j], Bs + (ks * 16) * BNP + warp_n * WN + j * 16, BNP);
#pragma unroll
            for (int i = 0; i < FM; ++i)
#pragma unroll
                for (int j = 0; j < FN; ++j)
                    wmma::mma_sync(acc[i][j], af[i], bf[j], acc[i][j]);
        }
        __syncthreads();
    }

    // ---- staged fp32 writeout ----
    constexpr int BNPF = BN + 8;
    float* Cs = sbuf_f;
#pragma unroll
    for (int i = 0; i < FM; ++i)
#pragma unroll
        for (int j = 0; j < FN; ++j)
            wmma::store_matrix_sync(Cs + (warp_m * 32 + i * 16) * BNPF + warp_n * WN + j * 16,
                                    acc[i][j], BNPF, wmma::mem_row_major);
    __syncthreads();

#pragma unroll
    for (int i = tid; i < BM * BN / 4; i += 256) {
        const int row = i / (BN / 4), cc = (i % (BN / 4)) * 4;
        const int grow = m0 + row;
        if (grow < M) {
            float4 v = *reinterpret_cast<const float4*>(Cs + row * BNPF + cc);
            const float4 bb = *reinterpret_cast<const float4*>(bias + cc);
            if (FUSED) {
                const float swv  = sw[grow];
                const float invd = 1.f / fmaxf(deg[grow], 1.f);
                const float4 pp  = *reinterpret_cast<const float4*>(P + (size_t)grow * BN + cc);
                v.x = 0.5f * (fmaxf((v.x + swv * bb.x) * invd, 0.f) + pp.x);
                v.y = 0.5f * (fmaxf((v.y + swv * bb.y) * invd, 0.f) + pp.y);
                v.z = 0.5f * (fmaxf((v.z + swv * bb.z) * invd, 0.f) + pp.z);
                v.w = 0.5f * (fmaxf((v.w + swv * bb.w) * invd, 0.f) + pp.w);
            } else { v.x += bb.x; v.y += bb.y; v.z += bb.z; v.w += bb.w; }
            *reinterpret_cast<float4*>(C + (size_t)grow * BN + cc) = v;
            if (WH) {
                union { __half2 h[2]; uint2 u; } pk;
                pk.h[0] = __floats2half2_rn(v.x, v.y);
                pk.h[1] = __floats2half2_rn(v.z, v.w);
                *reinterpret_cast<uint2*>(H + (size_t)grow * (BN / 2) + (cc >> 1)) = pk.u;
            }
        }
    }
}

// ---------------------------------------------------------------------------
extern "C" void kernel_launch(void* const* d_in, const int* in_sizes, int n_in,
                              void* d_out, int out_size)
{
    const float* feat = (const float*)d_in[0];
    const int* src0[2] = {(const int*)d_in[1], (const int*)d_in[3]};
    const int* dst0[2] = {(const int*)d_in[2], (const int*)d_in[4]};
    const int* src1[2] = {(const int*)d_in[5], (const int*)d_in[7]};
    const int* dst1[2] = {(const int*)d_in[6], (const int*)d_in[8]};
    const int E0 = in_sizes[1];
    const int E1 = in_sizes[5];

    const int b = n_in - 14;
    const float* Win  = (const float*)d_in[b + 0];
    const float* b_in = (const float*)d_in[b + 1];
    const float* na1  = (const float*)d_in[b + 2];
    const float* ea1  = (const float*)d_in[b + 3];
    const float* ia1  = (const float*)d_in[b + 4];
    const float* W1   = (const float*)d_in[b + 5];
    const float* b1   = (const float*)d_in[b + 6];
    const float* na2  = (const float*)d_in[b + 7];
    const float* ea2  = (const float*)d_in[b + 8];
    const float* ia2  = (const float*)d_in[b + 9];
    const float* W2   = (const float*)d_in[b + 10];
    const float* b2   = (const float*)d_in[b + 11];
    const float* Wout = (const float*)d_in[b + 12];
    const float* bout = (const float*)d_in[b + 13];

    const int F = in_sizes[b + 0] / (2 * D);  // 256
    const int n_src0 = in_sizes[0] / F;       // 100000

    float4 *z0, *z1, *z2, *P4;
    __half *feath, *wrh;
    __half2 *soneh, *z2h;
    float *sw, *deg, *pi_src, *pi_dst;
    float2 *pe_src, *pe_dst, *nalpha;
    int *cnt, *rank, *row[4], *col[4];
    cudaGetSymbolAddress((void**)&z0, g_z0);
    cudaGetSymbolAddress((void**)&z1, g_z1);
    cudaGetSymbolAddress((void**)&z2, g_z2);
    cudaGetSymbolAddress((void**)&feath, g_feath);
    cudaGetSymbolAddress((void**)&soneh, g_soneh);
    cudaGetSymbolAddress((void**)&z2h, g_z2h);
    cudaGetSymbolAddress((void**)&P4, g_p);
    cudaGetSymbolAddress((void**)&sw, g_sw);
    cudaGetSymbolAddress((void**)&deg, g_deg);
    cudaGetSymbolAddress((void**)&pe_src, g_pe_src);
    cudaGetSymbolAddress((void**)&pe_dst, g_pe_dst);
    cudaGetSymbolAddress((void**)&pi_src, g_pi_src);
    cudaGetSymbolAddress((void**)&pi_dst, g_pi_dst);
    cudaGetSymbolAddress((void**)&nalpha, g_nalpha);
    cudaGetSymbolAddress((void**)&wrh, g_wrh);
    cudaGetSymbolAddress((void**)&cnt, g_cnt);
    cudaGetSymbolAddress((void**)&rank, g_rank);
    cudaGetSymbolAddress((void**)&row[0], g_row0);
    cudaGetSymbolAddress((void**)&row[1], g_row1);
    cudaGetSymbolAddress((void**)&row[2], g_row2);
    cudaGetSymbolAddress((void**)&row[3], g_row3);
    cudaGetSymbolAddress((void**)&col[0], g_col0);
    cudaGetSymbolAddress((void**)&col[1], g_col1);
    cudaGetSymbolAddress((void**)&col[2], g_col2);
    cudaGetSymbolAddress((void**)&col[3], g_col3);

    const __half* Win_h  = wrh;
    const __half* W1_h   = wrh + 65536;
    const __half* W2_h   = wrh + 98304;
    const __half* Wout_h = wrh + 131072;

    float4*  z0m[2]   = {z0,   z0   + (size_t)NSRC0 * 32};
    float4*  z1m[2]   = {z1,   z1   + (size_t)NDST0 * 32};
    float4*  z2m[2]   = {z2,   z2   + (size_t)NDST1 * 32};
    __half2* sonehm[2] = {soneh, soneh + (size_t)NDST0 * 64};
    __half2* z2hm[2]   = {z2h,  z2h  + (size_t)NDST1 * 64};
    float4*  Pm[2]    = {P4,   P4   + (size_t)NDST0 * 32};
    float*   swm[2]   = {sw,   sw   + NDST0};
    float*   degm[2]  = {deg,  deg  + NDST0};

    constexpr int SMH128 = 64 * 136 * 4;   // 34816 B (Cs staging dominates)
    constexpr int SMH64  = 2 * (64 * 40 + 32 * 72) * 2;  // 19456 B
    cudaFuncSetAttribute(gemm64h_kernel<128, false, false>,
                         cudaFuncAttributeMaxDynamicSharedMemorySize, SMH128);
    cudaFuncSetAttribute(gemm64h_kernel<128, true, false>,
                         cudaFuncAttributeMaxDynamicSharedMemorySize, SMH128);
    cudaFuncSetAttribute(gemm64h_kernel<128, true, true>,
                         cudaFuncAttributeMaxDynamicSharedMemorySize, SMH128);
    cudaFuncSetAttribute(gemm64h_kernel<64, false, false>,
                         cudaFuncAttributeMaxDynamicSharedMemorySize, SMH64);

    float* out = (float*)d_out;
    const int Etot = 2 * E0 + 2 * E1;

    // ---- prepasses + CSR hist/scan ----
    round_weights_kernel<<<576, 256>>>(Win, W1, W2, Wout, wrh);
    feat_half_kernel<<<(n_src0 * 64 + 255) / 256, 256>>>(
        (const float4*)feat, feath, n_src0 * 64);
    cudaMemsetAsync(cnt, 0, sizeof(int) * (2 * NDST0 + 2 * NDST1));
    hist4_kernel<<<(Etot + 255) / 256, 256>>>(dst0[0], dst0[1], dst1[0], dst1[1],
                                              E0, E1, cnt, rank);
    scan4_kernel<<<4, 1024>>>(cnt, row[0], row[1], row[2], row[3]);

    // ---- Input GEMM (fp16 A/B, fp32 C) ----
    {
        ModeArgsH ma = {feath, feath,
                        Win_h, Win_h + (size_t)F * D, b_in, b_in + D,
                        (float*)z0m[0], (float*)z0m[1],
                        nullptr, nullptr, nullptr, nullptr, nullptr, nullptr,
                        nullptr, nullptr};
        gemm64h_kernel<128, false, false>
            <<<dim3((n_src0 + 63) / 64, 2), 256, SMH128>>>(ma, n_src0, F);
    }

    fill4_kernel<<<(Etot + 255) / 256, 256>>>(src0[0], dst0[0], src0[1], dst0[1],
                                              src1[0], dst1[0], src1[1], dst1[1],
                                              E0, E1, rank,
                                              row[0], row[1], row[2], row[3],
                                              col[0], col[1], col[2], col[3]);

    // ---- Layer 1: per-mode sequential proj -> agg ----
    for (int m = 0; m < 2; ++m) {
        proj2_kernel<<<dim3((n_src0 * 32 + 255) / 256, 1), 256>>>(
            z0, (size_t)NSRC0 * 32, n_src0, NDST0, m,
            na1, ea1, ia1, pe_src, pe_dst, pi_src, pi_dst, nalpha);
        agg2_kernel<<<dim3((NDST0 * 32 + 255) / 256, 1), 256>>>(
            NDST0, m, row[0], col[0], row[1], col[1],
            z0, (size_t)NSRC0 * 32,
            pe_src, pe_dst, pi_src, pi_dst, nalpha, soneh, P4, sw, deg);
    }

    // ---- Layer 1 GEMM ----
    {
        ModeArgsH ma = {(const __half*)sonehm[0], (const __half*)sonehm[1],
                        W1_h, W1_h + (size_t)D * D, b1, b1 + D,
                        (float*)z1m[0], (float*)z1m[1],
                        (const float*)Pm[0], (const float*)Pm[1],
                        swm[0], swm[1], degm[0], degm[1],
                        nullptr, nullptr};
        gemm64h_kernel<128, true, false>
            <<<dim3((NDST0 + 63) / 64, 2), 256, SMH128>>>(ma, NDST0, D);
    }

    // ---- Layer 2: proj + agg ----
    proj2_kernel<<<dim3((NDST0 * 32 + 255) / 256, 2), 256>>>(
        z1, (size_t)NDST0 * 32, NDST0, NDST1, 0,
        na2, ea2, ia2, pe_src, pe_dst, pi_src, pi_dst, nalpha);
    agg2_kernel<<<dim3((NDST1 * 32 + 255) / 256, 2), 256>>>(
        NDST1, 0, row[2], col[2], row[3], col[3],
        z1, (size_t)NDST0 * 32,
        pe_src, pe_dst, pi_src, pi_dst, nalpha, soneh, P4, sw, deg);

    // ---- Layer 2 GEMM (emits fp16 z2 for the out GEMM) ----
    {
        ModeArgsH ma = {(const __half*)sonehm[0], (const __half*)sonehm[1],
                        W2_h, W2_h + (size_t)D * D, b2, b2 + D,
                        (float*)z2m[0], (float*)z2m[1],
                        (const float*)Pm[0], (const float*)Pm[1],
                        swm[0], swm[1], degm[0], degm[1],
                        z2hm[0], z2hm[1]};
        gemm64h_kernel<128, true, true>
            <<<dim3((NDST1 + 63) / 64, 2), 256, SMH128>>>(ma, NDST1, D);
    }

    // ---- Output GEMM ----
    {
        ModeArgsH ma = {(const __half*)z2hm[0], (const __half*)z2hm[1],
                        Wout_h, Wout_h + (size_t)D * OUTD, bout, bout + OUTD,
                        out, out + (size_t)NDST1 * OUTD,
                        nullptr, nullptr, nullptr, nullptr, nullptr, nullptr,
                        nullptr, nullptr};
        gemm64h_kernel<64, false, false>
            <<<dim3((NDST1 + 63) / 64, 2), 256, SMH64>>>(ma, NDST1, D);
    }
    (void)out_size;
}